// round 1
// baseline (speedup 1.0000x reference)
#include <cuda_runtime.h>
#include <cstdint>

// Problem constants
#define NB   8          // batch
#define TPD  2048       // TP
#define ED   4096       // E
#define SD   8          // S
#define TD   16384      // T = TP*S
#define CD   64         // C
#define VD   17         // V+1
#define OUTROWS 131072  // T*S

// Scratch (device globals; no allocation allowed)
__device__ float g_WeffT[8 * 8 * ED];   // [s0][s][e]  -> 1 MB
__device__ float g_beff[8];             // b2 + sum_c b1[c]*W2[c,s]
__device__ int   g_bucket[64 * 2048];   // [(n*8+s0)][slot] = (r<<16)|tp
__device__ int   g_bcount[64];

// ---------------------------------------------------------------------------
// K0: Weff[e,s0,s] = sum_c W1[e,c,s0]*W2[c,0,s]; stored transposed [s0][s][e].
//     Also beff and bucket-count zeroing (runs first each replay).
// ---------------------------------------------------------------------------
__global__ void k0_weff(const float* __restrict__ W1, const float* __restrict__ W2,
                        const float* __restrict__ b1, const float* __restrict__ b2) {
    int e = blockIdx.x;           // 0..4095
    int tid = threadIdx.x;        // 64 threads
    __shared__ float w1row[512];  // W1[e, :, :]
    __shared__ float w2s[512];    // W2[:, 0, :]
    for (int i = tid; i < 512; i += 64) {
        w1row[i] = W1[e * 512 + i];
        w2s[i]   = W2[i];
    }
    __syncthreads();
    int s0 = tid >> 3, s = tid & 7;
    float acc = 0.f;
#pragma unroll
    for (int c = 0; c < 64; c++)
        acc += w1row[c * 8 + s0] * w2s[c * 8 + s];
    g_WeffT[(s0 * 8 + s) * ED + e] = acc;

    if (e == 0) {
        g_bcount[tid] = 0;  // exactly 64 entries
        if (tid < 8) {
            float a = 0.f;
#pragma unroll
            for (int c = 0; c < 64; c++) a += b1[c] * w2s[c * 8 + tid];
            g_beff[tid] = a + b2[0];
        }
    }
}

// ---------------------------------------------------------------------------
// K1: per-batch: idx = argmax(depth) (first max of a sorted array), masked
//     stream compaction of value==2 positions, bucketed by s0 = t&7.
//     One block per batch, 512 threads, 32 elements/thread.
// ---------------------------------------------------------------------------
__global__ void k1_prep(const int* __restrict__ value, const int* __restrict__ depth) {
    int n = blockIdx.x;
    int tid = threadIdx.x;
    const int* dep = depth + n * TD;
    const int* val = value + n * TD;

    int maxv = dep[TD - 1];
    __shared__ int s_idx;
    if (tid == 0) s_idx = TD;
    __syncthreads();
    for (int t = tid; t < TD; t += 512) {
        if (dep[t] == maxv && (t == 0 || dep[t - 1] < maxv)) atomicMin(&s_idx, t);
    }
    __syncthreads();
    int idx = s_idx;

    int base = tid * 32;
    unsigned mb = 0;
    int cnt = 0;
#pragma unroll
    for (int j = 0; j < 32; j++) {
        int t = base + j;
        bool m = (t < idx) && (val[t] == 2);
        mb |= ((unsigned)m) << j;
        cnt += (int)m;
    }
    // block exclusive scan over per-thread counts (512 threads = 16 warps)
    int lane = tid & 31, wid = tid >> 5;
    int v = cnt;
#pragma unroll
    for (int o = 1; o < 32; o <<= 1) {
        int u = __shfl_up_sync(0xffffffffu, v, o);
        if (lane >= o) v += u;
    }
    __shared__ int wsum[16];
    if (lane == 31) wsum[wid] = v;
    __syncthreads();
    if (tid < 32) {
        int w = (tid < 16) ? wsum[tid] : 0;
#pragma unroll
        for (int o = 1; o < 16; o <<= 1) {
            int u = __shfl_up_sync(0xffffffffu, w, o);
            if (lane >= o) w += u;
        }
        if (tid < 16) wsum[tid] = w;
    }
    __syncthreads();
    int warpbase = (wid == 0) ? 0 : wsum[wid - 1];
    int r = warpbase + v - cnt;  // exclusive prefix = rank of first masked elem

    for (int j = 0; j < 32; j++) {
        if ((mb >> j) & 1u) {
            int t = base + j;
            int s0 = t & 7, tp = t >> 3;
            int slot = atomicAdd(&g_bcount[n * 8 + s0], 1);
            g_bucket[(n * 8 + s0) * 2048 + slot] = (r << 16) | tp;
            r++;
        }
    }
}

// ---------------------------------------------------------------------------
// K2: default fill: out[n,j,v] = b2 * W3[v]  (rows beyond count have y=0)
// ---------------------------------------------------------------------------
__global__ void k2_fill(float* __restrict__ out, const float* __restrict__ b2,
                        const float* __restrict__ W3, int total) {
    int i = blockIdx.x * blockDim.x + threadIdx.x;
    if (i >= total) return;
    int v = i % VD;
    out[i] = b2[0] * W3[v];
}

// ---------------------------------------------------------------------------
// K3: bucketed GEMM: for each masked row (rank r, source tp, bucket s0):
//       y2[s] = sum_e x[n,tp,e] * WeffT[s0][s][e] + beff[s]
//       out[n, r*8+s, v] = y2[s] * W3[v]
//     Block: 64 rows x 8 s, K tiled by 64 through smem. 256 threads,
//     each owns (s, mq) -> rows mq and mq+32.
// ---------------------------------------------------------------------------
#define KT 64
__global__ __launch_bounds__(256) void k3_heavy(const float* __restrict__ x,
                                                const float* __restrict__ W3,
                                                float* __restrict__ out) {
    int n = blockIdx.z, s0 = blockIdx.y;
    int bucket = n * 8 + s0;
    int bcnt = g_bcount[bucket];
    int row0 = blockIdx.x * 64;
    if (row0 >= bcnt) return;

    int tid = threadIdx.x;
    __shared__ __align__(16) float Xs[64][68];  // padded: stride 272B (16B-aligned, conflict-free)
    __shared__ __align__(16) float Ws[8][68];
    __shared__ int sr[64];
    __shared__ int stp[64];
    __shared__ float w3s[VD];

    if (tid < 64) {
        int gr = row0 + tid;
        if (gr < bcnt) {
            int p = g_bucket[bucket * 2048 + gr];
            sr[tid]  = p >> 16;
            stp[tid] = p & 0xFFFF;
        } else {
            sr[tid] = -1;
            stp[tid] = 0;
        }
    }
    if (tid < VD) w3s[tid] = W3[tid];
    __syncthreads();

    int s = tid & 7, mq = tid >> 3;  // mq in 0..31
    float acc0 = 0.f, acc1 = 0.f;
    const float* xb = x + (size_t)n * TPD * ED;
    const float* wb = g_WeffT + (size_t)s0 * 8 * ED;

    for (int k0 = 0; k0 < ED; k0 += KT) {
        // load X tile: 64 rows x 64 floats = 1024 float4, 4 per thread
#pragma unroll
        for (int i = 0; i < 4; i++) {
            int f = tid + i * 256;
            int row = f >> 4, q = f & 15;
            float4 xv = *(const float4*)(xb + (size_t)stp[row] * ED + k0 + q * 4);
            *(float4*)&Xs[row][q * 4] = xv;
        }
        // load W tile: 8 rows x 64 floats = 128 float4
        if (tid < 128) {
            int srow = tid >> 4, q = tid & 15;
            float4 wv = *(const float4*)(wb + srow * ED + k0 + q * 4);
            *(float4*)&Ws[srow][q * 4] = wv;
        }
        __syncthreads();
#pragma unroll
        for (int kk = 0; kk < KT; kk += 4) {
            float4 w = *(const float4*)&Ws[s][kk];
            float4 a = *(const float4*)&Xs[mq][kk];
            float4 b = *(const float4*)&Xs[mq + 32][kk];
            acc0 += a.x * w.x; acc0 += a.y * w.y; acc0 += a.z * w.z; acc0 += a.w * w.w;
            acc1 += b.x * w.x; acc1 += b.y * w.y; acc1 += b.z * w.z; acc1 += b.w * w.w;
        }
        __syncthreads();
    }

    // epilogue: y2 = acc + beff[s]; out row j = r*8+s: out[j,v] = y2*W3[v]
    float be = g_beff[s];
    float* y2s = &Xs[0][0];  // reuse (all compute reads finished at last sync)
    y2s[mq * 8 + s]        = acc0 + be;
    y2s[(mq + 32) * 8 + s] = acc1 + be;
    __syncthreads();

    size_t outn = (size_t)n * OUTROWS * VD;
    for (int idx = tid; idx < 64 * 8 * VD; idx += 256) {
        int m = idx / (8 * VD);
        int rr = sr[m];
        if (rr < 0) continue;
        int q = idx - m * (8 * VD);
        int ss = q / VD;
        int vv = q - ss * VD;
        out[outn + (size_t)rr * 8 * VD + q] = y2s[m * 8 + ss] * w3s[vv];
    }
}

// ---------------------------------------------------------------------------
extern "C" void kernel_launch(void* const* d_in, const int* in_sizes, int n_in,
                              void* d_out, int out_size) {
    const float* x     = (const float*)d_in[0];
    const int*   value = (const int*)d_in[1];   // jax default x64-off: int32
    const int*   depth = (const int*)d_in[2];
    // d_in[3] = pos, unused by the reference output
    const float* W1    = (const float*)d_in[4];
    const float* b1    = (const float*)d_in[5];
    const float* W2    = (const float*)d_in[6];
    const float* b2    = (const float*)d_in[7];
    const float* W3    = (const float*)d_in[8];
    float* out = (float*)d_out;

    k0_weff<<<ED, 64>>>(W1, W2, b1, b2);
    k1_prep<<<NB, 512>>>(value, depth);
    int total = out_size;  // 8*131072*17
    k2_fill<<<(total + 255) / 256, 256>>>(out, b2, W3, total);
    k3_heavy<<<dim3(32, 8, NB), 256>>>(x, W3, out);
}

// round 2
// speedup vs baseline: 1.5862x; 1.5862x over previous
#include <cuda_runtime.h>
#include <cstdint>

// Problem constants
#define NB   8          // batch
#define TPD  2048       // TP
#define ED   4096       // E
#define SD   8          // S
#define TD   16384      // T = TP*S
#define CD   64         // C
#define VD   17         // V+1
#define OUTROWS 131072  // T*S

// Scratch (device globals; no allocation allowed)
__device__ float g_WeffT[8 * 8 * ED];   // [s0][s][e]  -> 1 MB
__device__ float g_beff[8];             // b2 + sum_c b1[c]*W2[c,s]
__device__ int   g_bucket[64 * 2048];   // [(n*8+s0)][slot] = (r<<16)|tp
__device__ int   g_bcount[64];

// ---------------------------------------------------------------------------
// cp.async helpers
// ---------------------------------------------------------------------------
__device__ __forceinline__ void ldgsts16(void* dst, const void* src) {
    unsigned saddr = (unsigned)__cvta_generic_to_shared(dst);
    asm volatile("cp.async.cg.shared.global [%0], [%1], 16;\n" :: "r"(saddr), "l"(src));
}
__device__ __forceinline__ void cp_commit() {
    asm volatile("cp.async.commit_group;\n" ::: "memory");
}
template <int N>
__device__ __forceinline__ void cp_wait() {
    asm volatile("cp.async.wait_group %0;\n" :: "n"(N) : "memory");
}

// ---------------------------------------------------------------------------
// K0: Weff[e,s0,s] = sum_c W1[e,c,s0]*W2[c,0,s]; stored transposed [s0][s][e].
//     Also beff and bucket-count zeroing (runs first each replay).
// ---------------------------------------------------------------------------
__global__ void k0_weff(const float* __restrict__ W1, const float* __restrict__ W2,
                        const float* __restrict__ b1, const float* __restrict__ b2) {
    int e = blockIdx.x;           // 0..4095
    int tid = threadIdx.x;        // 64 threads
    __shared__ float w1row[512];  // W1[e, :, :]
    __shared__ float w2s[512];    // W2[:, 0, :]
    for (int i = tid; i < 512; i += 64) {
        w1row[i] = W1[e * 512 + i];
        w2s[i]   = W2[i];
    }
    __syncthreads();
    int s0 = tid >> 3, s = tid & 7;
    float acc = 0.f;
#pragma unroll
    for (int c = 0; c < 64; c++)
        acc += w1row[c * 8 + s0] * w2s[c * 8 + s];
    g_WeffT[(s0 * 8 + s) * ED + e] = acc;

    if (e == 0) {
        g_bcount[tid] = 0;  // exactly 64 entries
        if (tid < 8) {
            float a = 0.f;
#pragma unroll
            for (int c = 0; c < 64; c++) a += b1[c] * w2s[c * 8 + tid];
            g_beff[tid] = a + b2[0];
        }
    }
}

// ---------------------------------------------------------------------------
// K1: per-batch argmax(depth) + masked stream compaction bucketed by s0=t&7.
// ---------------------------------------------------------------------------
__global__ void k1_prep(const int* __restrict__ value, const int* __restrict__ depth) {
    int n = blockIdx.x;
    int tid = threadIdx.x;
    const int* dep = depth + n * TD;
    const int* val = value + n * TD;

    int maxv = dep[TD - 1];
    __shared__ int s_idx;
    if (tid == 0) s_idx = TD;
    __syncthreads();
    for (int t = tid; t < TD; t += 512) {
        if (dep[t] == maxv && (t == 0 || dep[t - 1] < maxv)) atomicMin(&s_idx, t);
    }
    __syncthreads();
    int idx = s_idx;

    int base = tid * 32;
    unsigned mb = 0;
    int cnt = 0;
#pragma unroll
    for (int j = 0; j < 32; j++) {
        int t = base + j;
        bool m = (t < idx) && (val[t] == 2);
        mb |= ((unsigned)m) << j;
        cnt += (int)m;
    }
    int lane = tid & 31, wid = tid >> 5;
    int v = cnt;
#pragma unroll
    for (int o = 1; o < 32; o <<= 1) {
        int u = __shfl_up_sync(0xffffffffu, v, o);
        if (lane >= o) v += u;
    }
    __shared__ int wsum[16];
    if (lane == 31) wsum[wid] = v;
    __syncthreads();
    if (tid < 32) {
        int w = (tid < 16) ? wsum[tid] : 0;
#pragma unroll
        for (int o = 1; o < 16; o <<= 1) {
            int u = __shfl_up_sync(0xffffffffu, w, o);
            if (lane >= o) w += u;
        }
        if (tid < 16) wsum[tid] = w;
    }
    __syncthreads();
    int warpbase = (wid == 0) ? 0 : wsum[wid - 1];
    int r = warpbase + v - cnt;

    for (int j = 0; j < 32; j++) {
        if ((mb >> j) & 1u) {
            int t = base + j;
            int s0 = t & 7, tp = t >> 3;
            int slot = atomicAdd(&g_bcount[n * 8 + s0], 1);
            g_bucket[(n * 8 + s0) * 2048 + slot] = (r << 16) | tp;
            r++;
        }
    }
}

// ---------------------------------------------------------------------------
// K2: default fill: out[n,j,v] = b2 * W3[v]
// ---------------------------------------------------------------------------
__global__ void k2_fill(float* __restrict__ out, const float* __restrict__ b2,
                        const float* __restrict__ W3, int total) {
    int i = blockIdx.x * blockDim.x + threadIdx.x;
    if (i >= total) return;
    int v = i % VD;
    out[i] = b2[0] * W3[v];
}

// ---------------------------------------------------------------------------
// K3: bucketed GEMM, cp.async double-buffered, register tile RM=4 x RN=2.
//     Block: 64 rows x 8 s, 64 threads. tid -> rg = tid&15, sg = tid>>4.
//     Thread owns rows {rg, rg+16, rg+32, rg+48} and s in {sg, sg+4}.
// ---------------------------------------------------------------------------
#define KT 64
#define MROWS 64
#define XPAD 76   // row stride in floats (16B aligned; stride-16 rows -> <=2-way)

__global__ __launch_bounds__(64) void k3_heavy(const float* __restrict__ x,
                                               const float* __restrict__ W3,
                                               float* __restrict__ out) {
    int n = blockIdx.z, s0 = blockIdx.y;
    int bucket = n * 8 + s0;
    int bcnt = g_bcount[bucket];
    int row0 = blockIdx.x * MROWS;
    if (row0 >= bcnt) return;

    int tid = threadIdx.x;
    __shared__ __align__(16) float Xs[2][MROWS][XPAD];
    __shared__ __align__(16) float Ws[2][8][XPAD];
    __shared__ int sr[MROWS];
    __shared__ int stp[MROWS];
    __shared__ float w3s[VD];
    __shared__ float y2s[MROWS][8];

    // row metadata (64 threads == 64 rows)
    {
        int gr = row0 + tid;
        if (gr < bcnt) {
            int p = g_bucket[bucket * 2048 + gr];
            sr[tid]  = p >> 16;
            stp[tid] = p & 0xFFFF;
        } else {
            sr[tid] = -1;
            stp[tid] = 0;
        }
        if (tid < VD) w3s[tid] = W3[tid];
    }
    __syncthreads();

    const float* xb = x + (size_t)n * TPD * ED;
    const float* wb = g_WeffT + (size_t)s0 * 8 * ED;

    int col = tid & 15;          // 16B chunk column within 64-float tile row
    int rbase = tid >> 4;        // loader row base (0..3)

    // Issue loads for tile `t` into buffer `b`
    auto load_tile = [&](int t, int b) {
        int k0 = t * KT;
#pragma unroll
        for (int i = 0; i < 16; i++) {
            int row = rbase + 4 * i;  // 0..63
            ldgsts16(&Xs[b][row][col * 4],
                     xb + (size_t)stp[row] * ED + k0 + col * 4);
        }
#pragma unroll
        for (int i = 0; i < 2; i++) {
            int row = rbase + 4 * i;  // 0..7
            ldgsts16(&Ws[b][row][col * 4], wb + row * ED + k0 + col * 4);
        }
        cp_commit();
    };

    load_tile(0, 0);

    int rg = tid & 15, sg = tid >> 4;  // sg in 0..3
    float acc[4][2];
#pragma unroll
    for (int i = 0; i < 4; i++) { acc[i][0] = 0.f; acc[i][1] = 0.f; }

    const int NTILES = ED / KT;  // 64
    for (int t = 0; t < NTILES; t++) {
        int b = t & 1;
        if (t + 1 < NTILES) {
            load_tile(t + 1, b ^ 1);
            cp_wait<1>();
        } else {
            cp_wait<0>();
        }
        __syncthreads();

#pragma unroll
        for (int kk = 0; kk < KT; kk += 4) {
            float4 w0 = *(const float4*)&Ws[b][sg][kk];
            float4 w1 = *(const float4*)&Ws[b][sg + 4][kk];
#pragma unroll
            for (int i = 0; i < 4; i++) {
                float4 xv = *(const float4*)&Xs[b][rg + 16 * i][kk];
                acc[i][0] += xv.x * w0.x; acc[i][0] += xv.y * w0.y;
                acc[i][0] += xv.z * w0.z; acc[i][0] += xv.w * w0.w;
                acc[i][1] += xv.x * w1.x; acc[i][1] += xv.y * w1.y;
                acc[i][1] += xv.z * w1.z; acc[i][1] += xv.w * w1.w;
            }
        }
        __syncthreads();
    }

    // epilogue: y2 = acc + beff[s]; out row j = r*8+s: out[j,v] = y2*W3[v]
    float be0 = g_beff[sg];
    float be1 = g_beff[sg + 4];
#pragma unroll
    for (int i = 0; i < 4; i++) {
        y2s[rg + 16 * i][sg]     = acc[i][0] + be0;
        y2s[rg + 16 * i][sg + 4] = acc[i][1] + be1;
    }
    __syncthreads();

    size_t outn = (size_t)n * OUTROWS * VD;
    for (int idx = tid; idx < MROWS * 8 * VD; idx += 64) {
        int m = idx / (8 * VD);
        int rr = sr[m];
        if (rr < 0) continue;
        int q = idx - m * (8 * VD);
        int ss = q / VD;
        int vv = q - ss * VD;
        out[outn + (size_t)rr * 8 * VD + q] = y2s[m][ss] * w3s[vv];
    }
}

// ---------------------------------------------------------------------------
extern "C" void kernel_launch(void* const* d_in, const int* in_sizes, int n_in,
                              void* d_out, int out_size) {
    const float* x     = (const float*)d_in[0];
    const int*   value = (const int*)d_in[1];   // jax default x64-off: int32
    const int*   depth = (const int*)d_in[2];
    // d_in[3] = pos, unused by the reference output
    const float* W1    = (const float*)d_in[4];
    const float* b1    = (const float*)d_in[5];
    const float* W2    = (const float*)d_in[6];
    const float* b2    = (const float*)d_in[7];
    const float* W3    = (const float*)d_in[8];
    float* out = (float*)d_out;

    k0_weff<<<ED, 64>>>(W1, W2, b1, b2);
    k1_prep<<<NB, 512>>>(value, depth);
    int total = out_size;  // 8*131072*17
    k2_fill<<<(total + 255) / 256, 256>>>(out, b2, W3, total);
    k3_heavy<<<dim3(32, 8, NB), 64>>>(x, W3, out);
}